// round 13
// baseline (speedup 1.0000x reference)
#include <cuda_runtime.h>
#include <cstdint>

// ChessboardLayer: (B,H,W,C)=(32,256,256,32) fp32 space-to-depth into 8x8 cells.
// Pure 4KiB-block transpose:
//   in  chunk id q = br*256 + i*8 + c
//   out chunk id o = br*256 + c*32 + i
//
// FINAL: write-major layout + 256-bit global accesses (sm_100+
// ld/st.global.v8.b32 -> LDG.E.256/STG.E.256) + .cs streaming policy.
// Each CTA owns 4 consecutive OUTPUT chunks (16 KiB contiguous write);
// each thread moves 64 B as 2 independent 256-bit load/store pairs.
//
// Measured floor: 74.6us kernel / 6.45 TB/s = 80.7% of HBM3e spec — the
// chip's mixed read+write stream ceiling for this irreducible 512 MiB
// zero-reuse permutation. Confirmed across 11 variants (granularity,
// orientation, persistence, MLP 1-8, occupancy 62-86%, cache policies,
// 128/256-bit width): all within 74.6-79.2us kernel.

__device__ __forceinline__ void ldg256cs(uint32_t r[8], const void* p) {
    asm volatile("ld.global.nc.cs.v8.b32 {%0,%1,%2,%3,%4,%5,%6,%7}, [%8];"
                 : "=r"(r[0]), "=r"(r[1]), "=r"(r[2]), "=r"(r[3]),
                   "=r"(r[4]), "=r"(r[5]), "=r"(r[6]), "=r"(r[7])
                 : "l"(p));
}
__device__ __forceinline__ void stg256cs(void* p, const uint32_t r[8]) {
    asm volatile("st.global.cs.v8.b32 [%0], {%1,%2,%3,%4,%5,%6,%7,%8};"
                 :: "l"(p),
                    "r"(r[0]), "r"(r[1]), "r"(r[2]), "r"(r[3]),
                    "r"(r[4]), "r"(r[5]), "r"(r[6]), "r"(r[7])
                 : "memory");
}

__global__ void __launch_bounds__(256, 8)
chessboard_kernel(const float* __restrict__ in, float* __restrict__ out) {
    unsigned obase = blockIdx.x * 4u;    // first output chunk id (chunk = 1024 floats)
    unsigned t     = threadIdx.x;

    // o = obase + k, k=0..3. Aligned 4-group: br, c shared; i = i0 + k.
    unsigned i0 = obase & 31u;
    unsigned c  = (obase >> 5) & 7u;
    unsigned br = obase >> 8;
    unsigned qbase = br * 256u + i0 * 8u + c;   // input chunk for k=0; +8 per k

    // CTA moves 4096 floats = 512 v8-words; thread t handles words t and t+256.
    unsigned k0 = t >> 7, j0 = t & 127u;        // w0 = t      -> k0 in {0,1}
    unsigned k1 = k0 + 2u;                      // w1 = t+256  -> k1 in {2,3}

    const float* pi0 = in + (size_t)(qbase + k0 * 8u) * 1024u + j0 * 8u;
    const float* pi1 = in + (size_t)(qbase + k1 * 8u) * 1024u + j0 * 8u;

    uint32_t a[8], b[8];
    ldg256cs(a, pi0);
    ldg256cs(b, pi1);

    float* po0 = out + (size_t)(obase + k0) * 1024u + j0 * 8u;
    float* po1 = out + (size_t)(obase + k1) * 1024u + j0 * 8u;
    stg256cs(po0, a);
    stg256cs(po1, b);
}

extern "C" void kernel_launch(void* const* d_in, const int* in_sizes, int n_in,
                              void* d_out, int out_size) {
    const float* in  = (const float*)d_in[0];
    float*       out = (float*)d_out;
    // 65536 output chunks / 4 per CTA = 16384 CTAs
    chessboard_kernel<<<16384, 256>>>(in, out);
}

// round 14
// speedup vs baseline: 1.0059x; 1.0059x over previous
#include <cuda_runtime.h>
#include <cstdint>

// ChessboardLayer: (B,H,W,C)=(32,256,256,32) fp32 space-to-depth into 8x8 cells.
// Pure 4KiB-block transpose:
//   in  chunk id q = br*256 + i*8 + c
//   out chunk id o = br*256 + c*32 + i
//
// FINAL (best repeated measurements of the session): write-major layout +
// 256-bit global accesses (sm_100+ ld/st.global.v8.b32 ->
// LDG.E.256/STG.E.256), default cache policy (measured marginally better
// and more consistent than .cs at this width: 74.62/74.66us vs 74.66/75.49us).
// Each CTA owns 4 consecutive OUTPUT chunks (16 KiB contiguous write);
// each thread moves 64 B as 2 independent 256-bit load/store pairs.
//
// Measured floor: 74.6us kernel / 6.45 TB/s = 80.7% of HBM3e spec — the
// chip's mixed read+write stream ceiling for this irreducible 512 MiB
// zero-reuse permutation. Confirmed across 12 variants (granularity,
// orientation, persistence, MLP 1-8, occupancy 62-86%, cache policies,
// 128/256-bit width): all within 74.6-79.2us kernel / ~82us bench.

__device__ __forceinline__ void ldg256(uint32_t r[8], const void* p) {
    asm volatile("ld.global.nc.v8.b32 {%0,%1,%2,%3,%4,%5,%6,%7}, [%8];"
                 : "=r"(r[0]), "=r"(r[1]), "=r"(r[2]), "=r"(r[3]),
                   "=r"(r[4]), "=r"(r[5]), "=r"(r[6]), "=r"(r[7])
                 : "l"(p));
}
__device__ __forceinline__ void stg256(void* p, const uint32_t r[8]) {
    asm volatile("st.global.v8.b32 [%0], {%1,%2,%3,%4,%5,%6,%7,%8};"
                 :: "l"(p),
                    "r"(r[0]), "r"(r[1]), "r"(r[2]), "r"(r[3]),
                    "r"(r[4]), "r"(r[5]), "r"(r[6]), "r"(r[7])
                 : "memory");
}

__global__ void __launch_bounds__(256, 8)
chessboard_kernel(const float* __restrict__ in, float* __restrict__ out) {
    unsigned obase = blockIdx.x * 4u;    // first output chunk id (chunk = 1024 floats)
    unsigned t     = threadIdx.x;

    // o = obase + k, k=0..3. Aligned 4-group: br, c shared; i = i0 + k.
    unsigned i0 = obase & 31u;
    unsigned c  = (obase >> 5) & 7u;
    unsigned br = obase >> 8;
    unsigned qbase = br * 256u + i0 * 8u + c;   // input chunk for k=0; +8 per k

    // CTA moves 4096 floats = 512 v8-words; thread t handles words t and t+256.
    unsigned k0 = t >> 7, j0 = t & 127u;        // w0 = t      -> k0 in {0,1}
    unsigned k1 = k0 + 2u;                      // w1 = t+256  -> k1 in {2,3}

    const float* pi0 = in + (size_t)(qbase + k0 * 8u) * 1024u + j0 * 8u;
    const float* pi1 = in + (size_t)(qbase + k1 * 8u) * 1024u + j0 * 8u;

    uint32_t a[8], b[8];
    ldg256(a, pi0);
    ldg256(b, pi1);

    float* po0 = out + (size_t)(obase + k0) * 1024u + j0 * 8u;
    float* po1 = out + (size_t)(obase + k1) * 1024u + j0 * 8u;
    stg256(po0, a);
    stg256(po1, b);
}

extern "C" void kernel_launch(void* const* d_in, const int* in_sizes, int n_in,
                              void* d_out, int out_size) {
    const float* in  = (const float*)d_in[0];
    float*       out = (float*)d_out;
    // 65536 output chunks / 4 per CTA = 16384 CTAs
    chessboard_kernel<<<16384, 256>>>(in, out);
}